// round 14
// baseline (speedup 1.0000x reference)
#include <cuda_runtime.h>
#include <cuda_fp16.h>

#define NMAX 50000
#define EMAX 800000
#define AGG_GRID 740   // 148 SMs x 5 blocks: one full resident wave

// ---- scratch (device globals; no allocation allowed) ----
__device__ __align__(16) float g_bufA[NMAX * 96];
__device__ __align__(16) float g_bufB[NMAX * 96];
__device__ __align__(16) float g_t[NMAX * 96];
__device__ float g_dis[NMAX];
__device__ float g_r[NMAX];                  // rowsum of A_hat (self + edge weights)
__device__ int   g_counts[NMAX];             // zero at load; scan re-zeroes after use
__device__ int   g_rowptr[NMAX + 1];
__device__ int   g_cursor[NMAX];
__device__ __align__(16) int2 g_meta[EMAX];  // (src, bitcast(weight))
__device__ float g_statsA[256];              // [0..128) sum, [128..256) sumsq
__device__ float g_statsB[256];

// ---------------- CSR build ----------------

__global__ void count_kernel(const int* __restrict__ dst, int* counts, int E) {
    int e = blockIdx.x * blockDim.x + threadIdx.x;
    if (e < E) atomicAdd(&counts[dst[e]], 1);
}

__global__ void scan_kernel(int* __restrict__ counts, int* __restrict__ row_ptr,
                            int* __restrict__ cursor, float* __restrict__ dis, int n) {
    __shared__ int part[1024];
    int tid = threadIdx.x;
    int chunk = (n + 1023) / 1024;
    int beg = tid * chunk;
    int end = min(beg + chunk, n);
    int s = 0;
    for (int i = beg; i < end; i++) s += counts[i];
    part[tid] = s;
    __syncthreads();
    for (int off = 1; off < 1024; off <<= 1) {
        int v = part[tid];
        int add = (tid >= off) ? part[tid - off] : 0;
        __syncthreads();
        part[tid] = v + add;
        __syncthreads();
    }
    int run = (tid > 0) ? part[tid - 1] : 0;
    for (int i = beg; i < end; i++) {
        int c = counts[i];
        counts[i] = 0;                       // reset for next call (replay-safe)
        row_ptr[i] = run;
        cursor[i] = run;
        dis[i] = rsqrtf((float)c + 1.0f);
        run += c;
    }
    if (tid == 1023) row_ptr[n] = part[1023];
}

// ---------------- GEMM body: 256 threads / 64 rows, 4-way column split ----------------
// Encoder (DEC=0): t[row] = (AFF ? in*sc+sh : in) @ W        (acc init = sh@W)
// Decoder (DEC=1): out[row] = (AFF ? z*sc : z) @ W + r*(sh@W) + b   [+ optional RELU]

template <int FI, int FIS, int FO, int FOS, bool AFF, bool ZERO, bool DEC, bool RELU>
__device__ __forceinline__ void gemm_body(
        int bid, int tid,
        const float* __restrict__ x, const float* __restrict__ W,
        const float* __restrict__ g, const float* __restrict__ be,
        const float* __restrict__ stats_prev, float* __restrict__ stats_cur,
        const float* __restrict__ rsum, const float* __restrict__ bvec,
        float* __restrict__ t, int n,
        float* sW, float* s_tc, float* s_b, float* s_sc, float* s_sh) {
    if (AFF) {
        if (tid < FI) {
            float inv_n = 1.0f / (float)n;
            float mu = stats_prev[tid] * inv_n;
            float var = stats_prev[128 + tid] * inv_n - mu * mu;
            float s = g[tid] * rsqrtf(var + 1e-5f);
            s_sc[tid] = s;
            s_sh[tid] = be[tid] - mu * s;
        }
        __syncthreads();
    }
    if (ZERO && bid == 0) stats_cur[tid] = 0.0f;
    for (int idx = tid; idx < FIS * FOS; idx += 256) {
        int k = idx / FOS;
        int c = idx - k * FOS;
        float v = 0.0f;
        if (k < FI && c < FO) {
            v = __ldg(&W[k * FO + c]);
            if (AFF) v *= s_sc[k];
        }
        sW[idx] = v;
    }
    if (tid < FOS) {
        float tv = 0.0f;
        if (AFF && tid < FO) {
#pragma unroll 8
            for (int k = 0; k < FI; k++) tv += s_sh[k] * __ldg(&W[k * FO + tid]);
        }
        s_tc[tid] = tv;
        if (DEC) s_b[tid] = (tid < FO) ? __ldg(&bvec[tid]) : 0.0f;
    }
    __syncthreads();

    int row = bid * 64 + (tid >> 2);
    int h = tid & 3;
    if (row >= n) return;
    const float4* xr = (const float4*)(x + (size_t)row * FIS);
    constexpr int NG = FOS / 4;
    constexpr int MG = (NG + 3) / 4;
    constexpr int NK = FIS / 4;
    unsigned long long acc[MG * 2];
    float rv = 0.0f;
    if (DEC && AFF) rv = __ldg(&rsum[row]);
#pragma unroll
    for (int gi = 0; gi < MG; gi++) {
        int gg = h + 4 * gi;
        if (gg < NG) {
            if (!DEC) {
                acc[2 * gi]     = ((const unsigned long long*)s_tc)[gg * 2];
                acc[2 * gi + 1] = ((const unsigned long long*)s_tc)[gg * 2 + 1];
            } else {
                float2 a0, a1;
                a0.x = fmaf(rv, s_tc[gg * 4 + 0], s_b[gg * 4 + 0]);
                a0.y = fmaf(rv, s_tc[gg * 4 + 1], s_b[gg * 4 + 1]);
                a1.x = fmaf(rv, s_tc[gg * 4 + 2], s_b[gg * 4 + 2]);
                a1.y = fmaf(rv, s_tc[gg * 4 + 3], s_b[gg * 4 + 3]);
                acc[2 * gi]     = *(unsigned long long*)&a0;
                acc[2 * gi + 1] = *(unsigned long long*)&a1;
            }
        }
    }
    float4 xv = __ldg(&xr[0]);
#pragma unroll 1
    for (int k4 = 0; k4 < NK; k4++) {
        float4 xn;
        if (k4 + 1 < NK) xn = __ldg(&xr[k4 + 1]);
#pragma unroll
        for (int j = 0; j < 4; j++) {
            float xk = (j == 0) ? xv.x : (j == 1) ? xv.y : (j == 2) ? xv.z : xv.w;
            unsigned long long a2;
            asm("mov.b64 %0, {%1, %1};" : "=l"(a2) : "r"(__float_as_uint(xk)));
            const float* wr = &sW[(k4 * 4 + j) * FOS];
#pragma unroll
            for (int gi = 0; gi < MG; gi++) {
                int gg = h + 4 * gi;
                if (gg < NG) {
                    ulonglong2 w2 = *(const ulonglong2*)(wr + gg * 4);
                    asm("fma.rn.f32x2 %0, %1, %2, %0;" : "+l"(acc[2 * gi]) : "l"(a2), "l"(w2.x));
                    asm("fma.rn.f32x2 %0, %1, %2, %0;" : "+l"(acc[2 * gi + 1]) : "l"(a2), "l"(w2.y));
                }
            }
        }
        xv = xn;
    }
    float* tr = t + (size_t)row * FOS;
#pragma unroll
    for (int gi = 0; gi < MG; gi++) {
        int gg = h + 4 * gi;
        if (gg < NG) {
            if (DEC && RELU) {
                float2* f0 = (float2*)&acc[2 * gi];
                float2* f1 = (float2*)&acc[2 * gi + 1];
                f0->x = fmaxf(f0->x, 0.f); f0->y = fmaxf(f0->y, 0.f);
                f1->x = fmaxf(f1->x, 0.f); f1->y = fmaxf(f1->y, 0.f);
            }
            ulonglong2 v;
            v.x = acc[2 * gi];
            v.y = acc[2 * gi + 1];
            *(ulonglong2*)&tr[gg * 4] = v;
        }
    }
}

template <int FI, int FIS, int FO, int FOS, bool AFF, bool ZERO, bool DEC, bool RELU>
__global__ void __launch_bounds__(256) gemm_kernel(
        const float* __restrict__ x, const float* __restrict__ W,
        const float* __restrict__ g, const float* __restrict__ be,
        const float* __restrict__ stats_prev, float* __restrict__ stats_cur,
        const float* __restrict__ rsum, const float* __restrict__ bvec,
        float* __restrict__ t, int n) {
    __shared__ __align__(16) float sW[FIS * FOS];
    __shared__ __align__(16) float s_tc[FOS];
    __shared__ __align__(16) float s_b[FOS];
    __shared__ float s_sc[96], s_sh[96];
    gemm_body<FI, FIS, FO, FOS, AFF, ZERO, DEC, RELU>(
        blockIdx.x, threadIdx.x, x, W, g, be, stats_prev, stats_cur, rsum, bvec, t, n,
        sW, s_tc, s_b, s_sc, s_sh);
}

// ---- fused gemm(L1) + scatter ----
__global__ void __launch_bounds__(256) fused_gemm1_scatter(
        const float* __restrict__ x, const float* __restrict__ W1,
        float* __restrict__ stats_cur, float* __restrict__ t, int n, int gb,
        const int* __restrict__ src, const int* __restrict__ dst,
        const float* __restrict__ dis, int* __restrict__ cursor,
        int2* __restrict__ meta, int E) {
    __shared__ __align__(16) float sW[88 * 72];
    __shared__ __align__(16) float s_tc[72];
    __shared__ __align__(16) float s_b[72];
    __shared__ float s_sc[96], s_sh[96];
    if ((int)blockIdx.x < gb) {
        gemm_body<88, 88, 70, 72, false, true, false, false>(
            blockIdx.x, threadIdx.x, x, W1, nullptr, nullptr, nullptr, stats_cur,
            nullptr, nullptr, t, n, sW, s_tc, s_b, s_sc, s_sh);
    } else {
        int e = (blockIdx.x - gb) * 256 + threadIdx.x;
        if (e < E) {
            int s = src[e];
            int d = dst[e];
            int pos = atomicAdd(&cursor[d], 1);
            meta[pos] = make_int2(s, __float_as_int(dis[s] * dis[d]));
        }
    }
}

// ---------------- CSR aggregation ----------------

__device__ __forceinline__ void fma4(float4& a, float4 v, float w) {
    a.x += v.x * w; a.y += v.y * w; a.z += v.z * w; a.w += v.w * w;
}
__device__ __forceinline__ void stat4(float4& ps, float4& pq, float4 v) {
    ps.x += v.x; pq.x += v.x * v.x;
    ps.y += v.y; pq.y += v.y * v.y;
    ps.z += v.z; pq.z += v.z * v.z;
    ps.w += v.w; pq.w += v.w * v.w;
}

// ---- unpacked (FOS > 64): channel-per-lane float4, shfl meta, unroll 4 ----
template <int FO, int FOS, bool BIAS, bool RS, bool SIN, bool WR>
__global__ void __launch_bounds__(256, 5) agg_kernel(
        const int* __restrict__ rp, const int2* __restrict__ meta,
        const float* __restrict__ t, const float* __restrict__ dis,
        const float* __restrict__ b, float* __restrict__ out,
        float* __restrict__ stats, float* __restrict__ r_out, int n) {
    constexpr bool ST = RS || SIN;
    __shared__ float ssum[ST ? FO : 1];
    __shared__ float ssq[ST ? FO : 1];
    if (ST) {
        for (int i = threadIdx.x; i < FO; i += blockDim.x) { ssum[i] = 0.0f; ssq[i] = 0.0f; }
        __syncthreads();
    }
    int lane = threadIdx.x & 31;
    int warp = (blockIdx.x * blockDim.x + threadIdx.x) >> 5;
    int nwarps = (gridDim.x * blockDim.x) >> 5;
    int cb = lane * 4;
    bool act = cb < FOS;
    float4 bias = make_float4(0.f, 0.f, 0.f, 0.f);
    if (BIAS) {
        if (cb + 0 < FO) bias.x = __ldg(&b[cb + 0]);
        if (cb + 1 < FO) bias.y = __ldg(&b[cb + 1]);
        if (cb + 2 < FO) bias.z = __ldg(&b[cb + 2]);
        if (cb + 3 < FO) bias.w = __ldg(&b[cb + 3]);
    }
    float4 psum = make_float4(0.f, 0.f, 0.f, 0.f);
    float4 psq = make_float4(0.f, 0.f, 0.f, 0.f);

    for (int i = warp; i < n; i += nwarps) {
        float dd = dis[i];
        float d2 = dd * dd;
        float4 acc = bias;
        if (act) {
            float4 sv = __ldg((const float4*)&t[(size_t)i * FOS + cb]);
            if (SIN) stat4(psum, psq, sv);
            fma4(acc, sv, d2);
        }
        float racc = 0.0f;
        int beg = __ldg(&rp[i]);
        int end = __ldg(&rp[i + 1]);
        for (int base = beg; base < end; base += 32) {
            int rem = min(32, end - base);
            int2 m = make_int2(0, 0);
            if (lane < rem) m = __ldg(&meta[base + lane]);
            int k = 0;
#pragma unroll 1
            for (; k + 4 <= rem; k += 4) {
                int s0 = __shfl_sync(0xffffffffu, m.x, k);
                int w0 = __shfl_sync(0xffffffffu, m.y, k);
                int s1 = __shfl_sync(0xffffffffu, m.x, k + 1);
                int w1 = __shfl_sync(0xffffffffu, m.y, k + 1);
                int s2 = __shfl_sync(0xffffffffu, m.x, k + 2);
                int w2 = __shfl_sync(0xffffffffu, m.y, k + 2);
                int s3 = __shfl_sync(0xffffffffu, m.x, k + 3);
                int w3 = __shfl_sync(0xffffffffu, m.y, k + 3);
                if (WR) racc += __int_as_float(w0) + __int_as_float(w1) +
                                __int_as_float(w2) + __int_as_float(w3);
                if (act) {
                    float4 v0 = __ldg((const float4*)&t[(size_t)s0 * FOS + cb]);
                    float4 v1 = __ldg((const float4*)&t[(size_t)s1 * FOS + cb]);
                    float4 v2 = __ldg((const float4*)&t[(size_t)s2 * FOS + cb]);
                    float4 v3 = __ldg((const float4*)&t[(size_t)s3 * FOS + cb]);
                    fma4(acc, v0, __int_as_float(w0));
                    fma4(acc, v1, __int_as_float(w1));
                    fma4(acc, v2, __int_as_float(w2));
                    fma4(acc, v3, __int_as_float(w3));
                }
            }
#pragma unroll 1
            for (; k < rem; k++) {
                int s0 = __shfl_sync(0xffffffffu, m.x, k);
                int w0 = __shfl_sync(0xffffffffu, m.y, k);
                if (WR) racc += __int_as_float(w0);
                if (act) {
                    float4 v0 = __ldg((const float4*)&t[(size_t)s0 * FOS + cb]);
                    fma4(acc, v0, __int_as_float(w0));
                }
            }
        }
        if (WR && lane == 0) r_out[i] = d2 + racc;

        if (act) {
            if (RS) {
                acc.x = fmaxf(acc.x, 0.f); acc.y = fmaxf(acc.y, 0.f);
                acc.z = fmaxf(acc.z, 0.f); acc.w = fmaxf(acc.w, 0.f);
                stat4(psum, psq, acc);
            }
            *(float4*)&out[(size_t)i * FOS + cb] = acc;
        }
    }

    if (ST) {
        if (act) {
            if (cb + 0 < FO) { atomicAdd(&ssum[cb + 0], psum.x); atomicAdd(&ssq[cb + 0], psq.x); }
            if (cb + 1 < FO) { atomicAdd(&ssum[cb + 1], psum.y); atomicAdd(&ssq[cb + 1], psq.y); }
            if (cb + 2 < FO) { atomicAdd(&ssum[cb + 2], psum.z); atomicAdd(&ssq[cb + 2], psq.z); }
            if (cb + 3 < FO) { atomicAdd(&ssum[cb + 3], psum.w); atomicAdd(&ssq[cb + 3], psq.w); }
        }
        __syncthreads();
        for (int i = threadIdx.x; i < FO; i += blockDim.x) {
            atomicAdd(&stats[i], ssum[i]);
            atomicAdd(&stats[128 + i], ssq[i]);
        }
    }
}

// ---- packed (FOS <= 64): two edges per warp, half-warp per edge ----
template <int FO, int FOS, bool BIAS, bool RS, bool SIN>
__global__ void __launch_bounds__(256, 5) agg2_kernel(
        const int* __restrict__ rp, const int2* __restrict__ meta,
        const float* __restrict__ t, const float* __restrict__ dis,
        const float* __restrict__ b, float* __restrict__ out,
        float* __restrict__ stats, int n) {
    static_assert(FOS <= 64 && FOS % 4 == 0, "agg2 needs FOS<=64");
    constexpr bool ST = RS || SIN;
    __shared__ float ssum[ST ? FO : 1];
    __shared__ float ssq[ST ? FO : 1];
    if (ST) {
        for (int i = threadIdx.x; i < FO; i += blockDim.x) { ssum[i] = 0.0f; ssq[i] = 0.0f; }
        __syncthreads();
    }
    int lane = threadIdx.x & 31;
    int sub = lane >> 4;
    int ln = lane & 15;
    int cb = ln * 4;
    bool act = cb < FOS;
    int warp = (blockIdx.x * blockDim.x + threadIdx.x) >> 5;
    int nwarps = (gridDim.x * blockDim.x) >> 5;

    float4 bias = make_float4(0.f, 0.f, 0.f, 0.f);
    if (BIAS) {
        if (cb + 0 < FO) bias.x = __ldg(&b[cb + 0]);
        if (cb + 1 < FO) bias.y = __ldg(&b[cb + 1]);
        if (cb + 2 < FO) bias.z = __ldg(&b[cb + 2]);
        if (cb + 3 < FO) bias.w = __ldg(&b[cb + 3]);
    }
    float4 psum = make_float4(0.f, 0.f, 0.f, 0.f);
    float4 psq = make_float4(0.f, 0.f, 0.f, 0.f);

    for (int i = warp; i < n; i += nwarps) {
        float dd = dis[i];
        float d2 = dd * dd;
        float4 acc = (sub == 0) ? bias : make_float4(0.f, 0.f, 0.f, 0.f);
        if (act && sub == 1) {
            float4 sv = __ldg((const float4*)&t[(size_t)i * FOS + cb]);
            if (SIN) stat4(psum, psq, sv);
            fma4(acc, sv, d2);
        }

        int beg = __ldg(&rp[i]);
        int end = __ldg(&rp[i + 1]);
        for (int base = beg; base < end; base += 32) {
            int rem = min(32, end - base);
            int2 m = make_int2(0, 0);
            if (lane < rem) m = __ldg(&meta[base + lane]);
            int k = 0;
#pragma unroll 1
            for (; k + 8 <= rem; k += 8) {
                int i0 = k + sub, i1 = k + 2 + sub, i2 = k + 4 + sub, i3 = k + 6 + sub;
                int s0 = __shfl_sync(0xffffffffu, m.x, i0);
                int w0 = __shfl_sync(0xffffffffu, m.y, i0);
                int s1 = __shfl_sync(0xffffffffu, m.x, i1);
                int w1 = __shfl_sync(0xffffffffu, m.y, i1);
                int s2 = __shfl_sync(0xffffffffu, m.x, i2);
                int w2 = __shfl_sync(0xffffffffu, m.y, i2);
                int s3 = __shfl_sync(0xffffffffu, m.x, i3);
                int w3 = __shfl_sync(0xffffffffu, m.y, i3);
                if (act) {
                    float4 v0 = __ldg((const float4*)&t[(size_t)s0 * FOS + cb]);
                    float4 v1 = __ldg((const float4*)&t[(size_t)s1 * FOS + cb]);
                    float4 v2 = __ldg((const float4*)&t[(size_t)s2 * FOS + cb]);
                    float4 v3 = __ldg((const float4*)&t[(size_t)s3 * FOS + cb]);
                    fma4(acc, v0, __int_as_float(w0));
                    fma4(acc, v1, __int_as_float(w1));
                    fma4(acc, v2, __int_as_float(w2));
                    fma4(acc, v3, __int_as_float(w3));
                }
            }
#pragma unroll 1
            for (; k < rem; k += 2) {
                int idx = k + sub;
                bool on = idx < rem;
                int cidx = on ? idx : k;
                int s0 = __shfl_sync(0xffffffffu, m.x, cidx);
                int w0 = __shfl_sync(0xffffffffu, m.y, cidx);
                float wf = on ? __int_as_float(w0) : 0.0f;
                if (act) {
                    float4 v0 = __ldg((const float4*)&t[(size_t)s0 * FOS + cb]);
                    fma4(acc, v0, wf);
                }
            }
        }

        acc.x += __shfl_xor_sync(0xffffffffu, acc.x, 16);
        acc.y += __shfl_xor_sync(0xffffffffu, acc.y, 16);
        acc.z += __shfl_xor_sync(0xffffffffu, acc.z, 16);
        acc.w += __shfl_xor_sync(0xffffffffu, acc.w, 16);

        if (act && sub == 0) {
            if (RS) {
                acc.x = fmaxf(acc.x, 0.f); acc.y = fmaxf(acc.y, 0.f);
                acc.z = fmaxf(acc.z, 0.f); acc.w = fmaxf(acc.w, 0.f);
                stat4(psum, psq, acc);
            }
            *(float4*)&out[(size_t)i * FOS + cb] = acc;
        }
    }

    if (ST) {
        bool mine = act && (RS ? (sub == 0) : (sub == 1));
        if (mine) {
            if (cb + 0 < FO) { atomicAdd(&ssum[cb + 0], psum.x); atomicAdd(&ssq[cb + 0], psq.x); }
            if (cb + 1 < FO) { atomicAdd(&ssum[cb + 1], psum.y); atomicAdd(&ssq[cb + 1], psq.y); }
            if (cb + 2 < FO) { atomicAdd(&ssum[cb + 2], psum.z); atomicAdd(&ssq[cb + 2], psq.z); }
            if (cb + 3 < FO) { atomicAdd(&ssum[cb + 3], psum.w); atomicAdd(&ssq[cb + 3], psq.w); }
        }
        __syncthreads();
        for (int i = threadIdx.x; i < FO; i += blockDim.x) {
            atomicAdd(&stats[i], ssum[i]);
            atomicAdd(&stats[128 + i], ssq[i]);
        }
    }
}

// ---------------- host driver ----------------

extern "C" void kernel_launch(void* const* d_in, const int* in_sizes, int n_in,
                              void* d_out, int out_size) {
    const float* x = (const float*)d_in[0];
    const int* edge = (const int*)d_in[1];   // int32 (JAX x64 disabled)
    const float* W1 = (const float*)d_in[2];
    const float* b1 = (const float*)d_in[3];
    const float* W2 = (const float*)d_in[4];
    const float* b2 = (const float*)d_in[5];
    const float* W3 = (const float*)d_in[6];
    const float* b3 = (const float*)d_in[7];
    const float* W4 = (const float*)d_in[8];
    const float* b4 = (const float*)d_in[9];
    const float* W5 = (const float*)d_in[10];
    const float* b5 = (const float*)d_in[11];
    const float* W6 = (const float*)d_in[12];
    const float* b6 = (const float*)d_in[13];
    const float* g1 = (const float*)d_in[14];
    const float* be1 = (const float*)d_in[15];
    const float* g2 = (const float*)d_in[16];
    const float* be2 = (const float*)d_in[17];
    const float* g3 = (const float*)d_in[18];
    const float* be3 = (const float*)d_in[19];
    const float* g4 = (const float*)d_in[20];
    const float* be4 = (const float*)d_in[21];

    int n = in_sizes[0] / 88;
    int E = in_sizes[1] / 2;
    const int* src = edge;
    const int* dst = edge + E;

    float *bufA, *bufB, *t, *dis, *rr, *sA, *sB;
    int *counts, *rp, *cursor;
    int2* meta;
    cudaGetSymbolAddress((void**)&bufA, g_bufA);
    cudaGetSymbolAddress((void**)&bufB, g_bufB);
    cudaGetSymbolAddress((void**)&t, g_t);
    cudaGetSymbolAddress((void**)&dis, g_dis);
    cudaGetSymbolAddress((void**)&rr, g_r);
    cudaGetSymbolAddress((void**)&counts, g_counts);
    cudaGetSymbolAddress((void**)&rp, g_rowptr);
    cudaGetSymbolAddress((void**)&cursor, g_cursor);
    cudaGetSymbolAddress((void**)&meta, g_meta);
    cudaGetSymbolAddress((void**)&sA, g_statsA);
    cudaGetSymbolAddress((void**)&sB, g_statsB);

    float* out = (float*)d_out;
    int gb = (n + 63) / 64;
    int eb = (E + 255) / 256;

    // CSR build + L1 gemm fused with scatter
    count_kernel<<<eb, 256>>>(dst, counts, E);
    scan_kernel<<<1, 1024>>>(counts, rp, cursor, dis, n);
    fused_gemm1_scatter<<<gb + eb, 256>>>(x, W1, sA, t, n, gb, src, dst, dis, cursor, meta, E);

    // --- encoder (gemm then agg; bias/relu/stats in agg) ---
    agg_kernel<70, 72, true, true, false, true><<<AGG_GRID, 256>>>(rp, meta, t, dis, b1, bufA, sA, rr, n);
    gemm_kernel<70, 72, 60, 60, true, true, false, false><<<gb, 256>>>(bufA, W2, g1, be1, sA, sB, nullptr, nullptr, t, n);
    agg2_kernel<60, 60, true, true, false><<<AGG_GRID, 256>>>(rp, meta, t, dis, b2, bufB, sB, n);
    gemm_kernel<60, 60, 50, 52, true, false, false, false><<<gb, 256>>>(bufB, W3, g2, be2, sB, nullptr, nullptr, nullptr, t, n);
    agg2_kernel<50, 52, true, false, false><<<AGG_GRID, 256>>>(rp, meta, t, dis, b3, bufA, nullptr, n);

    // --- decoder (agg then gemm; agg on smaller input dim) ---
    agg2_kernel<50, 52, false, false, false><<<AGG_GRID, 256>>>(rp, meta, bufA, dis, nullptr, t, nullptr, n);
    gemm_kernel<50, 52, 60, 60, false, true, true, true><<<gb, 256>>>(t, W4, nullptr, nullptr, nullptr, sA, nullptr, b4, bufB, n);
    agg2_kernel<60, 60, false, false, true><<<AGG_GRID, 256>>>(rp, meta, bufB, dis, nullptr, t, sA, n);
    gemm_kernel<60, 60, 70, 72, true, true, true, true><<<gb, 256>>>(t, W5, g3, be3, sA, sB, rr, b5, bufA, n);
    agg_kernel<70, 72, false, false, true, false><<<AGG_GRID, 256>>>(rp, meta, bufA, dis, nullptr, t, sB, nullptr, n);
    gemm_kernel<70, 72, 88, 88, true, false, true, false><<<gb, 256>>>(t, W6, g4, be4, sB, nullptr, rr, b6, out, n);
}

// round 15
// speedup vs baseline: 1.2102x; 1.2102x over previous
#include <cuda_runtime.h>
#include <cuda_fp16.h>

#define NMAX 50000
#define EMAX 800000
#define AGG_GRID 740   // 148 SMs x 5 blocks: one full resident wave

// ---- scratch (device globals; no allocation allowed) ----
__device__ __align__(16) float g_bufA[NMAX * 96];
__device__ __align__(16) float g_bufB[NMAX * 96];
__device__ __align__(16) float g_t[NMAX * 96];
__device__ float g_dis[NMAX];
__device__ float g_r[NMAX];                  // rowsum of A_hat (self + edge weights)
__device__ int   g_counts[NMAX];             // zero at load; scan re-zeroes after use
__device__ int   g_rowptr[NMAX + 1];
__device__ int   g_cursor[NMAX];
__device__ __align__(16) int2 g_meta[EMAX];  // (src, bitcast(weight))
__device__ float g_statsA[256];              // [0..128) sum, [128..256) sumsq
__device__ float g_statsB[256];

// ---------------- CSR build ----------------

__global__ void count_kernel(const int* __restrict__ dst, int* counts, int E) {
    int e = blockIdx.x * blockDim.x + threadIdx.x;
    if (e < E) atomicAdd(&counts[dst[e]], 1);
}

__global__ void scan_kernel(int* __restrict__ counts, int* __restrict__ row_ptr,
                            int* __restrict__ cursor, float* __restrict__ dis, int n) {
    __shared__ int part[1024];
    int tid = threadIdx.x;
    int chunk = (n + 1023) / 1024;
    int beg = tid * chunk;
    int end = min(beg + chunk, n);
    int s = 0;
    for (int i = beg; i < end; i++) s += counts[i];
    part[tid] = s;
    __syncthreads();
    for (int off = 1; off < 1024; off <<= 1) {
        int v = part[tid];
        int add = (tid >= off) ? part[tid - off] : 0;
        __syncthreads();
        part[tid] = v + add;
        __syncthreads();
    }
    int run = (tid > 0) ? part[tid - 1] : 0;
    for (int i = beg; i < end; i++) {
        int c = counts[i];
        counts[i] = 0;                       // reset for next call (replay-safe)
        row_ptr[i] = run;
        cursor[i] = run;
        dis[i] = rsqrtf((float)c + 1.0f);
        run += c;
    }
    if (tid == 1023) row_ptr[n] = part[1023];
}

// ---------------- GEMM body: 256 threads / 128 rows, 2-way column split ----------------
// Encoder (DEC=0): t[row] = (AFF ? in*sc+sh : in) @ W        (acc init = sh@W)
// Decoder (DEC=1): out[row] = (AFF ? z*sc : z) @ W + r*(sh@W) + b   [+ optional RELU]

template <int FI, int FIS, int FO, int FOS, bool AFF, bool ZERO, bool DEC, bool RELU>
__device__ __forceinline__ void gemm_body(
        int bid, int tid,
        const float* __restrict__ x, const float* __restrict__ W,
        const float* __restrict__ g, const float* __restrict__ be,
        const float* __restrict__ stats_prev, float* __restrict__ stats_cur,
        const float* __restrict__ rsum, const float* __restrict__ bvec,
        float* __restrict__ t, int n,
        float* sW, float* s_tc, float* s_b, float* s_sc, float* s_sh) {
    if (AFF) {
        if (tid < FI) {
            float inv_n = 1.0f / (float)n;
            float mu = stats_prev[tid] * inv_n;
            float var = stats_prev[128 + tid] * inv_n - mu * mu;
            float s = g[tid] * rsqrtf(var + 1e-5f);
            s_sc[tid] = s;
            s_sh[tid] = be[tid] - mu * s;
        }
        __syncthreads();
    }
    if (ZERO && bid == 0) stats_cur[tid] = 0.0f;
    for (int idx = tid; idx < FIS * FOS; idx += 256) {
        int k = idx / FOS;
        int c = idx - k * FOS;
        float v = 0.0f;
        if (k < FI && c < FO) {
            v = __ldg(&W[k * FO + c]);
            if (AFF) v *= s_sc[k];
        }
        sW[idx] = v;
    }
    if (tid < FOS) {
        float tv = 0.0f;
        if (AFF && tid < FO) {
#pragma unroll 8
            for (int k = 0; k < FI; k++) tv += s_sh[k] * __ldg(&W[k * FO + tid]);
        }
        s_tc[tid] = tv;
        if (DEC) s_b[tid] = (tid < FO) ? __ldg(&bvec[tid]) : 0.0f;
    }
    __syncthreads();

    int row = bid * 128 + (tid >> 1);
    int h = tid & 1;
    if (row >= n) return;
    const float4* xr = (const float4*)(x + (size_t)row * FIS);
    constexpr int NG = FOS / 4;
    constexpr int MG = (NG + 1) / 2;
    constexpr int NK = FIS / 4;
    unsigned long long acc[MG * 2];
    float rv = 0.0f;
    if (DEC && AFF) rv = __ldg(&rsum[row]);
#pragma unroll
    for (int gi = 0; gi < MG; gi++) {
        int gg = h + 2 * gi;
        if (gg < NG) {
            if (!DEC) {
                acc[2 * gi]     = ((const unsigned long long*)s_tc)[gg * 2];
                acc[2 * gi + 1] = ((const unsigned long long*)s_tc)[gg * 2 + 1];
            } else {
                float2 a0, a1;
                a0.x = fmaf(rv, s_tc[gg * 4 + 0], s_b[gg * 4 + 0]);
                a0.y = fmaf(rv, s_tc[gg * 4 + 1], s_b[gg * 4 + 1]);
                a1.x = fmaf(rv, s_tc[gg * 4 + 2], s_b[gg * 4 + 2]);
                a1.y = fmaf(rv, s_tc[gg * 4 + 3], s_b[gg * 4 + 3]);
                acc[2 * gi]     = *(unsigned long long*)&a0;
                acc[2 * gi + 1] = *(unsigned long long*)&a1;
            }
        }
    }
    float4 xv = __ldg(&xr[0]);
#pragma unroll 1
    for (int k4 = 0; k4 < NK; k4++) {
        float4 xn;
        if (k4 + 1 < NK) xn = __ldg(&xr[k4 + 1]);
#pragma unroll
        for (int j = 0; j < 4; j++) {
            float xk = (j == 0) ? xv.x : (j == 1) ? xv.y : (j == 2) ? xv.z : xv.w;
            unsigned long long a2;
            asm("mov.b64 %0, {%1, %1};" : "=l"(a2) : "r"(__float_as_uint(xk)));
            const float* wr = &sW[(k4 * 4 + j) * FOS];
#pragma unroll
            for (int gi = 0; gi < MG; gi++) {
                int gg = h + 2 * gi;
                if (gg < NG) {
                    ulonglong2 w2 = *(const ulonglong2*)(wr + gg * 4);
                    asm("fma.rn.f32x2 %0, %1, %2, %0;" : "+l"(acc[2 * gi]) : "l"(a2), "l"(w2.x));
                    asm("fma.rn.f32x2 %0, %1, %2, %0;" : "+l"(acc[2 * gi + 1]) : "l"(a2), "l"(w2.y));
                }
            }
        }
        xv = xn;
    }
    float* tr = t + (size_t)row * FOS;
#pragma unroll
    for (int gi = 0; gi < MG; gi++) {
        int gg = h + 2 * gi;
        if (gg < NG) {
            if (DEC && RELU) {
                float2* f0 = (float2*)&acc[2 * gi];
                float2* f1 = (float2*)&acc[2 * gi + 1];
                f0->x = fmaxf(f0->x, 0.f); f0->y = fmaxf(f0->y, 0.f);
                f1->x = fmaxf(f1->x, 0.f); f1->y = fmaxf(f1->y, 0.f);
            }
            ulonglong2 v;
            v.x = acc[2 * gi];
            v.y = acc[2 * gi + 1];
            *(ulonglong2*)&tr[gg * 4] = v;
        }
    }
}

template <int FI, int FIS, int FO, int FOS, bool AFF, bool ZERO, bool DEC, bool RELU>
__global__ void __launch_bounds__(256) gemm_kernel(
        const float* __restrict__ x, const float* __restrict__ W,
        const float* __restrict__ g, const float* __restrict__ be,
        const float* __restrict__ stats_prev, float* __restrict__ stats_cur,
        const float* __restrict__ rsum, const float* __restrict__ bvec,
        float* __restrict__ t, int n) {
    __shared__ __align__(16) float sW[FIS * FOS];
    __shared__ __align__(16) float s_tc[FOS];
    __shared__ __align__(16) float s_b[FOS];
    __shared__ float s_sc[96], s_sh[96];
    gemm_body<FI, FIS, FO, FOS, AFF, ZERO, DEC, RELU>(
        blockIdx.x, threadIdx.x, x, W, g, be, stats_prev, stats_cur, rsum, bvec, t, n,
        sW, s_tc, s_b, s_sc, s_sh);
}

// ---- fused gemm(L1) + scatter ----
__global__ void __launch_bounds__(256) fused_gemm1_scatter(
        const float* __restrict__ x, const float* __restrict__ W1,
        float* __restrict__ stats_cur, float* __restrict__ t, int n, int gb,
        const int* __restrict__ src, const int* __restrict__ dst,
        const float* __restrict__ dis, int* __restrict__ cursor,
        int2* __restrict__ meta, int E) {
    __shared__ __align__(16) float sW[88 * 72];
    __shared__ __align__(16) float s_tc[72];
    __shared__ __align__(16) float s_b[72];
    __shared__ float s_sc[96], s_sh[96];
    if ((int)blockIdx.x < gb) {
        gemm_body<88, 88, 70, 72, false, true, false, false>(
            blockIdx.x, threadIdx.x, x, W1, nullptr, nullptr, nullptr, stats_cur,
            nullptr, nullptr, t, n, sW, s_tc, s_b, s_sc, s_sh);
    } else {
        int e = (blockIdx.x - gb) * 256 + threadIdx.x;
        if (e < E) {
            int s = src[e];
            int d = dst[e];
            int pos = atomicAdd(&cursor[d], 1);
            meta[pos] = make_int2(s, __float_as_int(dis[s] * dis[d]));
        }
    }
}

// ---------------- CSR aggregation ----------------

__device__ __forceinline__ void fma4(float4& a, float4 v, float w) {
    a.x += v.x * w; a.y += v.y * w; a.z += v.z * w; a.w += v.w * w;
}
__device__ __forceinline__ void stat4(float4& ps, float4& pq, float4 v) {
    ps.x += v.x; pq.x += v.x * v.x;
    ps.y += v.y; pq.y += v.y * v.y;
    ps.z += v.z; pq.z += v.z * v.z;
    ps.w += v.w; pq.w += v.w * v.w;
}

// ---- unpacked (FOS > 64): channel-per-lane float4, shfl meta, unroll 4 ----
template <int FO, int FOS, bool BIAS, bool RS, bool SIN, bool WR>
__global__ void __launch_bounds__(256, 5) agg_kernel(
        const int* __restrict__ rp, const int2* __restrict__ meta,
        const float* __restrict__ t, const float* __restrict__ dis,
        const float* __restrict__ b, float* __restrict__ out,
        float* __restrict__ stats, float* __restrict__ r_out, int n) {
    constexpr bool ST = RS || SIN;
    __shared__ float ssum[ST ? FO : 1];
    __shared__ float ssq[ST ? FO : 1];
    if (ST) {
        for (int i = threadIdx.x; i < FO; i += blockDim.x) { ssum[i] = 0.0f; ssq[i] = 0.0f; }
        __syncthreads();
    }
    int lane = threadIdx.x & 31;
    int warp = (blockIdx.x * blockDim.x + threadIdx.x) >> 5;
    int nwarps = (gridDim.x * blockDim.x) >> 5;
    int cb = lane * 4;
    bool act = cb < FOS;
    float4 bias = make_float4(0.f, 0.f, 0.f, 0.f);
    if (BIAS) {
        if (cb + 0 < FO) bias.x = __ldg(&b[cb + 0]);
        if (cb + 1 < FO) bias.y = __ldg(&b[cb + 1]);
        if (cb + 2 < FO) bias.z = __ldg(&b[cb + 2]);
        if (cb + 3 < FO) bias.w = __ldg(&b[cb + 3]);
    }
    float4 psum = make_float4(0.f, 0.f, 0.f, 0.f);
    float4 psq = make_float4(0.f, 0.f, 0.f, 0.f);

    for (int i = warp; i < n; i += nwarps) {
        float dd = dis[i];
        float d2 = dd * dd;
        float4 acc = bias;
        if (act) {
            float4 sv = __ldg((const float4*)&t[(size_t)i * FOS + cb]);
            if (SIN) stat4(psum, psq, sv);
            fma4(acc, sv, d2);
        }
        float racc = 0.0f;
        int beg = __ldg(&rp[i]);
        int end = __ldg(&rp[i + 1]);
        for (int base = beg; base < end; base += 32) {
            int rem = min(32, end - base);
            int2 m = make_int2(0, 0);
            if (lane < rem) m = __ldg(&meta[base + lane]);
            int k = 0;
#pragma unroll 1
            for (; k + 4 <= rem; k += 4) {
                int s0 = __shfl_sync(0xffffffffu, m.x, k);
                int w0 = __shfl_sync(0xffffffffu, m.y, k);
                int s1 = __shfl_sync(0xffffffffu, m.x, k + 1);
                int w1 = __shfl_sync(0xffffffffu, m.y, k + 1);
                int s2 = __shfl_sync(0xffffffffu, m.x, k + 2);
                int w2 = __shfl_sync(0xffffffffu, m.y, k + 2);
                int s3 = __shfl_sync(0xffffffffu, m.x, k + 3);
                int w3 = __shfl_sync(0xffffffffu, m.y, k + 3);
                if (WR) racc += __int_as_float(w0) + __int_as_float(w1) +
                                __int_as_float(w2) + __int_as_float(w3);
                if (act) {
                    float4 v0 = __ldg((const float4*)&t[(size_t)s0 * FOS + cb]);
                    float4 v1 = __ldg((const float4*)&t[(size_t)s1 * FOS + cb]);
                    float4 v2 = __ldg((const float4*)&t[(size_t)s2 * FOS + cb]);
                    float4 v3 = __ldg((const float4*)&t[(size_t)s3 * FOS + cb]);
                    fma4(acc, v0, __int_as_float(w0));
                    fma4(acc, v1, __int_as_float(w1));
                    fma4(acc, v2, __int_as_float(w2));
                    fma4(acc, v3, __int_as_float(w3));
                }
            }
#pragma unroll 1
            for (; k < rem; k++) {
                int s0 = __shfl_sync(0xffffffffu, m.x, k);
                int w0 = __shfl_sync(0xffffffffu, m.y, k);
                if (WR) racc += __int_as_float(w0);
                if (act) {
                    float4 v0 = __ldg((const float4*)&t[(size_t)s0 * FOS + cb]);
                    fma4(acc, v0, __int_as_float(w0));
                }
            }
        }
        if (WR && lane == 0) r_out[i] = d2 + racc;

        if (act) {
            if (RS) {
                acc.x = fmaxf(acc.x, 0.f); acc.y = fmaxf(acc.y, 0.f);
                acc.z = fmaxf(acc.z, 0.f); acc.w = fmaxf(acc.w, 0.f);
                stat4(psum, psq, acc);
            }
            *(float4*)&out[(size_t)i * FOS + cb] = acc;
        }
    }

    if (ST) {
        if (act) {
            if (cb + 0 < FO) { atomicAdd(&ssum[cb + 0], psum.x); atomicAdd(&ssq[cb + 0], psq.x); }
            if (cb + 1 < FO) { atomicAdd(&ssum[cb + 1], psum.y); atomicAdd(&ssq[cb + 1], psq.y); }
            if (cb + 2 < FO) { atomicAdd(&ssum[cb + 2], psum.z); atomicAdd(&ssq[cb + 2], psq.z); }
            if (cb + 3 < FO) { atomicAdd(&ssum[cb + 3], psum.w); atomicAdd(&ssq[cb + 3], psq.w); }
        }
        __syncthreads();
        for (int i = threadIdx.x; i < FO; i += blockDim.x) {
            atomicAdd(&stats[i], ssum[i]);
            atomicAdd(&stats[128 + i], ssq[i]);
        }
    }
}

// ---- packed (FOS <= 64): two edges per warp, half-warp per edge ----
template <int FO, int FOS, bool BIAS, bool RS, bool SIN>
__global__ void __launch_bounds__(256, 5) agg2_kernel(
        const int* __restrict__ rp, const int2* __restrict__ meta,
        const float* __restrict__ t, const float* __restrict__ dis,
        const float* __restrict__ b, float* __restrict__ out,
        float* __restrict__ stats, int n) {
    static_assert(FOS <= 64 && FOS % 4 == 0, "agg2 needs FOS<=64");
    constexpr bool ST = RS || SIN;
    __shared__ float ssum[ST ? FO : 1];
    __shared__ float ssq[ST ? FO : 1];
    if (ST) {
        for (int i = threadIdx.x; i < FO; i += blockDim.x) { ssum[i] = 0.0f; ssq[i] = 0.0f; }
        __syncthreads();
    }
    int lane = threadIdx.x & 31;
    int sub = lane >> 4;
    int ln = lane & 15;
    int cb = ln * 4;
    bool act = cb < FOS;
    int warp = (blockIdx.x * blockDim.x + threadIdx.x) >> 5;
    int nwarps = (gridDim.x * blockDim.x) >> 5;

    float4 bias = make_float4(0.f, 0.f, 0.f, 0.f);
    if (BIAS) {
        if (cb + 0 < FO) bias.x = __ldg(&b[cb + 0]);
        if (cb + 1 < FO) bias.y = __ldg(&b[cb + 1]);
        if (cb + 2 < FO) bias.z = __ldg(&b[cb + 2]);
        if (cb + 3 < FO) bias.w = __ldg(&b[cb + 3]);
    }
    float4 psum = make_float4(0.f, 0.f, 0.f, 0.f);
    float4 psq = make_float4(0.f, 0.f, 0.f, 0.f);

    for (int i = warp; i < n; i += nwarps) {
        float dd = dis[i];
        float d2 = dd * dd;
        float4 acc = (sub == 0) ? bias : make_float4(0.f, 0.f, 0.f, 0.f);
        if (act && sub == 1) {
            float4 sv = __ldg((const float4*)&t[(size_t)i * FOS + cb]);
            if (SIN) stat4(psum, psq, sv);
            fma4(acc, sv, d2);
        }

        int beg = __ldg(&rp[i]);
        int end = __ldg(&rp[i + 1]);
        for (int base = beg; base < end; base += 32) {
            int rem = min(32, end - base);
            int2 m = make_int2(0, 0);
            if (lane < rem) m = __ldg(&meta[base + lane]);
            int k = 0;
#pragma unroll 1
            for (; k + 8 <= rem; k += 8) {
                int i0 = k + sub, i1 = k + 2 + sub, i2 = k + 4 + sub, i3 = k + 6 + sub;
                int s0 = __shfl_sync(0xffffffffu, m.x, i0);
                int w0 = __shfl_sync(0xffffffffu, m.y, i0);
                int s1 = __shfl_sync(0xffffffffu, m.x, i1);
                int w1 = __shfl_sync(0xffffffffu, m.y, i1);
                int s2 = __shfl_sync(0xffffffffu, m.x, i2);
                int w2 = __shfl_sync(0xffffffffu, m.y, i2);
                int s3 = __shfl_sync(0xffffffffu, m.x, i3);
                int w3 = __shfl_sync(0xffffffffu, m.y, i3);
                if (act) {
                    float4 v0 = __ldg((const float4*)&t[(size_t)s0 * FOS + cb]);
                    float4 v1 = __ldg((const float4*)&t[(size_t)s1 * FOS + cb]);
                    float4 v2 = __ldg((const float4*)&t[(size_t)s2 * FOS + cb]);
                    float4 v3 = __ldg((const float4*)&t[(size_t)s3 * FOS + cb]);
                    fma4(acc, v0, __int_as_float(w0));
                    fma4(acc, v1, __int_as_float(w1));
                    fma4(acc, v2, __int_as_float(w2));
                    fma4(acc, v3, __int_as_float(w3));
                }
            }
#pragma unroll 1
            for (; k < rem; k += 2) {
                int idx = k + sub;
                bool on = idx < rem;
                int cidx = on ? idx : k;
                int s0 = __shfl_sync(0xffffffffu, m.x, cidx);
                int w0 = __shfl_sync(0xffffffffu, m.y, cidx);
                float wf = on ? __int_as_float(w0) : 0.0f;
                if (act) {
                    float4 v0 = __ldg((const float4*)&t[(size_t)s0 * FOS + cb]);
                    fma4(acc, v0, wf);
                }
            }
        }

        acc.x += __shfl_xor_sync(0xffffffffu, acc.x, 16);
        acc.y += __shfl_xor_sync(0xffffffffu, acc.y, 16);
        acc.z += __shfl_xor_sync(0xffffffffu, acc.z, 16);
        acc.w += __shfl_xor_sync(0xffffffffu, acc.w, 16);

        if (act && sub == 0) {
            if (RS) {
                acc.x = fmaxf(acc.x, 0.f); acc.y = fmaxf(acc.y, 0.f);
                acc.z = fmaxf(acc.z, 0.f); acc.w = fmaxf(acc.w, 0.f);
                stat4(psum, psq, acc);
            }
            *(float4*)&out[(size_t)i * FOS + cb] = acc;
        }
    }

    if (ST) {
        bool mine = act && (RS ? (sub == 0) : (sub == 1));
        if (mine) {
            if (cb + 0 < FO) { atomicAdd(&ssum[cb + 0], psum.x); atomicAdd(&ssq[cb + 0], psq.x); }
            if (cb + 1 < FO) { atomicAdd(&ssum[cb + 1], psum.y); atomicAdd(&ssq[cb + 1], psq.y); }
            if (cb + 2 < FO) { atomicAdd(&ssum[cb + 2], psum.z); atomicAdd(&ssq[cb + 2], psq.z); }
            if (cb + 3 < FO) { atomicAdd(&ssum[cb + 3], psum.w); atomicAdd(&ssq[cb + 3], psq.w); }
        }
        __syncthreads();
        for (int i = threadIdx.x; i < FO; i += blockDim.x) {
            atomicAdd(&stats[i], ssum[i]);
            atomicAdd(&stats[128 + i], ssq[i]);
        }
    }
}

// ---------------- host driver ----------------

extern "C" void kernel_launch(void* const* d_in, const int* in_sizes, int n_in,
                              void* d_out, int out_size) {
    const float* x = (const float*)d_in[0];
    const int* edge = (const int*)d_in[1];   // int32 (JAX x64 disabled)
    const float* W1 = (const float*)d_in[2];
    const float* b1 = (const float*)d_in[3];
    const float* W2 = (const float*)d_in[4];
    const float* b2 = (const float*)d_in[5];
    const float* W3 = (const float*)d_in[6];
    const float* b3 = (const float*)d_in[7];
    const float* W4 = (const float*)d_in[8];
    const float* b4 = (const float*)d_in[9];
    const float* W5 = (const float*)d_in[10];
    const float* b5 = (const float*)d_in[11];
    const float* W6 = (const float*)d_in[12];
    const float* b6 = (const float*)d_in[13];
    const float* g1 = (const float*)d_in[14];
    const float* be1 = (const float*)d_in[15];
    const float* g2 = (const float*)d_in[16];
    const float* be2 = (const float*)d_in[17];
    const float* g3 = (const float*)d_in[18];
    const float* be3 = (const float*)d_in[19];
    const float* g4 = (const float*)d_in[20];
    const float* be4 = (const float*)d_in[21];

    int n = in_sizes[0] / 88;
    int E = in_sizes[1] / 2;
    const int* src = edge;
    const int* dst = edge + E;

    float *bufA, *bufB, *t, *dis, *rr, *sA, *sB;
    int *counts, *rp, *cursor;
    int2* meta;
    cudaGetSymbolAddress((void**)&bufA, g_bufA);
    cudaGetSymbolAddress((void**)&bufB, g_bufB);
    cudaGetSymbolAddress((void**)&t, g_t);
    cudaGetSymbolAddress((void**)&dis, g_dis);
    cudaGetSymbolAddress((void**)&rr, g_r);
    cudaGetSymbolAddress((void**)&counts, g_counts);
    cudaGetSymbolAddress((void**)&rp, g_rowptr);
    cudaGetSymbolAddress((void**)&cursor, g_cursor);
    cudaGetSymbolAddress((void**)&meta, g_meta);
    cudaGetSymbolAddress((void**)&sA, g_statsA);
    cudaGetSymbolAddress((void**)&sB, g_statsB);

    float* out = (float*)d_out;
    int gb = (n + 127) / 128;
    int eb = (E + 255) / 256;

    // CSR build + L1 gemm fused with scatter
    count_kernel<<<eb, 256>>>(dst, counts, E);
    scan_kernel<<<1, 1024>>>(counts, rp, cursor, dis, n);
    fused_gemm1_scatter<<<gb + eb, 256>>>(x, W1, sA, t, n, gb, src, dst, dis, cursor, meta, E);

    // --- encoder (gemm then agg; bias/relu/stats in agg) ---
    agg_kernel<70, 72, true, true, false, true><<<AGG_GRID, 256>>>(rp, meta, t, dis, b1, bufA, sA, rr, n);
    gemm_kernel<70, 72, 60, 60, true, true, false, false><<<gb, 256>>>(bufA, W2, g1, be1, sA, sB, nullptr, nullptr, t, n);
    agg2_kernel<60, 60, true, true, false><<<AGG_GRID, 256>>>(rp, meta, t, dis, b2, bufB, sB, n);
    gemm_kernel<60, 60, 50, 52, true, false, false, false><<<gb, 256>>>(bufB, W3, g2, be2, sB, nullptr, nullptr, nullptr, t, n);
    agg2_kernel<50, 52, true, false, false><<<AGG_GRID, 256>>>(rp, meta, t, dis, b3, bufA, nullptr, n);

    // --- decoder (agg then gemm; agg on smaller input dim) ---
    agg2_kernel<50, 52, false, false, false><<<AGG_GRID, 256>>>(rp, meta, bufA, dis, nullptr, t, nullptr, n);
    gemm_kernel<50, 52, 60, 60, false, true, true, true><<<gb, 256>>>(t, W4, nullptr, nullptr, nullptr, sA, nullptr, b4, bufB, n);
    agg2_kernel<60, 60, false, false, true><<<AGG_GRID, 256>>>(rp, meta, bufB, dis, nullptr, t, sA, n);
    gemm_kernel<60, 60, 70, 72, true, true, true, true><<<gb, 256>>>(t, W5, g3, be3, sA, sB, rr, b5, bufA, n);
    agg_kernel<70, 72, false, false, true, false><<<AGG_GRID, 256>>>(rp, meta, bufA, dis, nullptr, t, sB, nullptr, n);
    gemm_kernel<70, 72, 88, 88, true, false, true, false><<<gb, 256>>>(t, W6, g4, be4, sB, nullptr, rr, b6, out, n);
}